// round 3
// baseline (speedup 1.0000x reference)
#include <cuda_runtime.h>
#include <cuda_bf16.h>

// Problem constants (from reference: B=32, A=4096, P=8388608, E=8)
#define Bn 32
#define An 4096
#define En 8

#define NB 256      // blocks
#define PT 256      // threads per block
#define PVEC 4      // pairs per thread per iteration (int4)
#define PITERS 32   // iterations per block
#define PAIRS_PER_ITER (PT * PVEC)             // 1024
#define PAIRS_PER_BLOCK (PAIRS_PER_ITER * PITERS)  // 32768 (NB*32768 = P exactly)

// Persistent device state. Zeroed at module load; the LAST block of every run
// resets them to 0 after writing the output, so each graph replay starts clean.
__device__ unsigned g_done;                 // too_close bitmask (monotone OR)
__device__ unsigned g_count;                // completion ticket counter
__device__ unsigned char g_engbig[Bn];      // written unconditionally each run

__global__ void __launch_bounds__(PT)
k_fused(const float* __restrict__ pos,
        const float* __restrict__ eng,
        const int* __restrict__ elm,
        const float* __restrict__ radius,
        const float* __restrict__ eng_atm,
        const int* __restrict__ nn,
        const int* __restrict__ ii,
        const int* __restrict__ jj,
        int P,
        float* __restrict__ out, int out_size) {
    __shared__ float s_rad[En];     // radius table (LDS ~29cyc vs L2 ~234)
    __shared__ unsigned s_mask;     // block's view of global done-mask
    __shared__ unsigned s_new;      // newly discovered bits this iteration
    __shared__ unsigned s_ticket;   // last-block detection
    __shared__ float s_red[PT / 32];

    int tid = threadIdx.x;
    int bid = blockIdx.x;

    if (tid < En) s_rad[tid] = radius[tid];
    if (tid == 0) { s_mask = __ldcg(&g_done); s_new = 0u; }
    __syncthreads();

    // ---- blocks 0..31: eng_big for structure b (others skip straight to pairs)
    if (bid < Bn) {
        __shared__ float s_atm[En];
        if (tid < En) s_atm[tid] = eng_atm[tid];
        __syncthreads();
        float s = 0.f;
        for (int a = tid; a < An; a += PT)
            s += s_atm[elm[bid * An + a]];
        #pragma unroll
        for (int o = 16; o > 0; o >>= 1)
            s += __shfl_down_sync(0xFFFFFFFFu, s, o);
        if ((tid & 31) == 0) s_red[tid >> 5] = s;
        __syncthreads();
        if (tid == 0) {
            float tot = 0.f;
            #pragma unroll
            for (int w = 0; w < PT / 32; ++w) tot += s_red[w];
            g_engbig[bid] = (eng[bid] >= tot) ? 1 : 0;
        }
    }

    // ---- pair phase: direct gathers, monotone-OR done-mask, early exit
    long long base = (long long)bid * PAIRS_PER_BLOCK;

    for (int it = 0; it < PITERS; ++it) {
        unsigned m = s_mask;             // uniform across block (post-sync)
        if (m == 0xFFFFFFFFu) break;     // every structure has a close pair

        long long idx = base + (long long)it * PAIRS_PER_ITER + tid * PVEC;
        unsigned local = 0u;

        if (idx + PVEC <= (long long)P) {
            int4 n4 = __ldg((const int4*)(nn + idx));
            int4 i4 = __ldg((const int4*)(ii + idx));
            int4 j4 = __ldg((const int4*)(jj + idx));
            int na[4] = {n4.x, n4.y, n4.z, n4.w};
            int ia[4] = {i4.x, i4.y, i4.z, i4.w};
            int ja[4] = {j4.x, j4.y, j4.z, j4.w};
            #pragma unroll
            for (int k = 0; k < 4; ++k) {
                int nb = na[k];
                if ((m >> nb) & 1u) continue;       // structure already flagged
                int ai = nb * An + ia[k];
                int aj = nb * An + ja[k];
                float ax = __ldg(pos + 3 * ai + 0);
                float ay = __ldg(pos + 3 * ai + 1);
                float az = __ldg(pos + 3 * ai + 2);
                float bx = __ldg(pos + 3 * aj + 0);
                float by = __ldg(pos + 3 * aj + 1);
                float bz = __ldg(pos + 3 * aj + 2);
                float rs = s_rad[__ldg(elm + ai)] + s_rad[__ldg(elm + aj)];
                float dx = bx - ax, dy = by - ay, dz = bz - az;
                float sod = dx * dx + dy * dy + dz * dz;
                if (rs * rs >= sod) local |= 1u << nb;
            }
        } else if (idx < (long long)P) {
            for (int k = 0; k < PVEC; ++k) {
                long long q = idx + k;
                if (q >= (long long)P) break;
                int nb = __ldg(nn + q);
                if ((m >> nb) & 1u) continue;
                int ai = nb * An + __ldg(ii + q);
                int aj = nb * An + __ldg(jj + q);
                float dx = __ldg(pos + 3 * aj + 0) - __ldg(pos + 3 * ai + 0);
                float dy = __ldg(pos + 3 * aj + 1) - __ldg(pos + 3 * ai + 1);
                float dz = __ldg(pos + 3 * aj + 2) - __ldg(pos + 3 * ai + 2);
                float sod = dx * dx + dy * dy + dz * dz;
                float rs = s_rad[__ldg(elm + ai)] + s_rad[__ldg(elm + aj)];
                if (rs * rs >= sod) local |= 1u << nb;
            }
        }

        local &= ~m;
        if (local) atomicOr(&s_new, local);
        __syncthreads();

        if (tid == 0) {
            unsigned nb2 = s_new;
            if (nb2) {
                unsigned old = atomicOr(&g_done, nb2);   // publish new bits
                s_mask = old | nb2;
                s_new = 0u;
            } else {
                s_mask = __ldcg(&g_done);                // cheap L2 poll
            }
        }
        __syncthreads();
    }

    // ---- completion: last block writes output and resets persistent state
    __threadfence();                 // make g_done / g_engbig writes visible
    __syncthreads();
    if (tid == 0) s_ticket = atomicAdd(&g_count, 1u);
    __syncthreads();

    if (s_ticket == (unsigned)(gridDim.x - 1)) {
        __threadfence();             // acquire side of the counter handshake
        unsigned m = atomicOr(&g_done, 0u);   // coherent read of final mask
        for (int b = tid; b < out_size; b += PT) {
            float v = 0.0f;
            if (b < Bn) {
                unsigned eb = ((const volatile unsigned char*)g_engbig)[b];
                v = (eb | ((m >> b) & 1u)) ? 1.0f : 0.0f;
            }
            out[b] = v;
        }
        __syncthreads();             // all output reads/writes done before reset
        if (tid == 0) {
            g_done = 0u;             // clean state for the next graph replay
            g_count = 0u;
        }
    }
}

// ---------------------------------------------------------------------------
// Inputs (metadata order): pos[B,A,3] f32, eng[B] f32, elm[B,A] i32,
// radius[E] f32, eng_atm[E] f32, n[P] i32, i[P] i32, j[P] i32.
// Output: float32[B] (0.0 / 1.0).
extern "C" void kernel_launch(void* const* d_in, const int* in_sizes, int n_in,
                              void* d_out, int out_size) {
    const float* pos     = (const float*)d_in[0];
    const float* eng     = (const float*)d_in[1];
    const int*   elm     = (const int*)d_in[2];
    const float* radius  = (const float*)d_in[3];
    const float* eng_atm = (const float*)d_in[4];
    const int*   nn      = (const int*)d_in[5];
    const int*   ii      = (const int*)d_in[6];
    const int*   jj      = (const int*)d_in[7];
    int P = in_sizes[5];

    k_fused<<<NB, PT>>>(pos, eng, elm, radius, eng_atm, nn, ii, jj, P,
                        (float*)d_out, out_size);
}

// round 4
// speedup vs baseline: 1.0577x; 1.0577x over previous
#include <cuda_runtime.h>
#include <cuda_bf16.h>

// Problem constants (from reference: B=32, A=4096, P=8388608, E=8)
#define Bn 32
#define An 4096
#define En 8

#define NB 256
#define PT 256
#define WPB (PT / 32)                 // 8 warps/block
#define NWARPS (NB * WPB)             // 2048
#define WCHUNK 4096                   // pairs per warp (NWARPS*WCHUNK = P)
#define WTILE 128                     // pairs per warp per iteration (32 lanes x int4)

// Persistent device state: zero at module load; last block resets after each
// run so every graph replay starts clean.
__device__ unsigned g_done;   // bit b set => out[b]=1 (eng_big OR too_close)
__device__ unsigned g_count;  // completion ticket

__global__ void __launch_bounds__(PT)
k_fused(const float* __restrict__ pos,
        const float* __restrict__ eng,
        const int* __restrict__ elm,
        const float* __restrict__ radius,
        const float* __restrict__ eng_atm,
        const int* __restrict__ nn,
        const int* __restrict__ ii,
        const int* __restrict__ jj,
        int P,
        float* __restrict__ out, int out_size) {
    __shared__ float s_rad[En];
    __shared__ unsigned s_ticket;

    const int tid  = threadIdx.x;
    const int bid  = blockIdx.x;
    const int wid  = tid >> 5;
    const int lane = tid & 31;

    if (tid < En) s_rad[tid] = radius[tid];
    __syncthreads();   // only block-wide sync before the epilogue

    // ---- eng_big: warp 0 of blocks 0..31 handles structure `bid`.
    // Publishes its bit straight into g_done (seed + output contribution).
    if (bid < Bn && wid == 0) {
        float av = __ldg(eng_atm + (lane & (En - 1)));  // lane e holds eng_atm[e]
        const int4* row = (const int4*)(elm + bid * An);
        float s = 0.f;
        #pragma unroll 4
        for (int t = lane; t < An / 4; t += 32) {
            int4 e4 = __ldg(row + t);
            s += __shfl_sync(0xFFFFFFFFu, av, e4.x & 7);
            s += __shfl_sync(0xFFFFFFFFu, av, e4.y & 7);
            s += __shfl_sync(0xFFFFFFFFu, av, e4.z & 7);
            s += __shfl_sync(0xFFFFFFFFu, av, e4.w & 7);
        }
        #pragma unroll
        for (int o = 16; o > 0; o >>= 1)
            s += __shfl_down_sync(0xFFFFFFFFu, s, o);
        s = __shfl_sync(0xFFFFFFFFu, s, 0);
        if (lane == 0 && __ldg(eng + bid) >= s)
            atomicOr(&g_done, 1u << bid);          // no return use -> RED
    }

    // ---- pair phase: per-warp autonomous loop, no block barriers.
    const int gw = bid * WPB + wid;                 // global warp id
    const long long base = (long long)gw * WCHUNK;

    for (int it = 0; it < WCHUNK / WTILE; ++it) {
        unsigned m = __ldcg(&g_done);               // warp-uniform broadcast load
        m = __shfl_sync(0xFFFFFFFFu, m, 0);
        if (m == 0xFFFFFFFFu) break;                // all structures resolved

        long long idx = base + (long long)it * WTILE + lane * 4;
        unsigned local = 0u;

        if (idx + 4 <= (long long)P) {
            int4 n4 = __ldg((const int4*)(nn + idx));
            int4 i4 = __ldg((const int4*)(ii + idx));
            int4 j4 = __ldg((const int4*)(jj + idx));
            int na[4] = {n4.x, n4.y, n4.z, n4.w};
            int ia[4] = {i4.x, i4.y, i4.z, i4.w};
            int ja[4] = {j4.x, j4.y, j4.z, j4.w};
            #pragma unroll
            for (int k = 0; k < 4; ++k) {
                int nb = na[k];
                if ((m >> nb) & 1u) continue;       // already flagged
                int ai = nb * An + ia[k];
                int aj = nb * An + ja[k];
                float ax = __ldg(pos + 3 * ai + 0);
                float ay = __ldg(pos + 3 * ai + 1);
                float az = __ldg(pos + 3 * ai + 2);
                float bx = __ldg(pos + 3 * aj + 0);
                float by = __ldg(pos + 3 * aj + 1);
                float bz = __ldg(pos + 3 * aj + 2);
                float rs = s_rad[__ldg(elm + ai)] + s_rad[__ldg(elm + aj)];
                float dx = bx - ax, dy = by - ay, dz = bz - az;
                float sod = dx * dx + dy * dy + dz * dz;
                if (rs * rs >= sod) local |= 1u << nb;
            }
        } else if (idx < (long long)P) {
            for (int k = 0; k < 4; ++k) {
                long long q = idx + k;
                if (q >= (long long)P) break;
                int nb = __ldg(nn + q);
                if ((m >> nb) & 1u) continue;
                int ai = nb * An + __ldg(ii + q);
                int aj = nb * An + __ldg(jj + q);
                float dx = __ldg(pos + 3 * aj + 0) - __ldg(pos + 3 * ai + 0);
                float dy = __ldg(pos + 3 * aj + 1) - __ldg(pos + 3 * ai + 1);
                float dz = __ldg(pos + 3 * aj + 2) - __ldg(pos + 3 * ai + 2);
                float sod = dx * dx + dy * dy + dz * dz;
                float rs = s_rad[__ldg(elm + ai)] + s_rad[__ldg(elm + aj)];
                if (rs * rs >= sod) local |= 1u << nb;
            }
        }

        unsigned wbits = __reduce_or_sync(0xFFFFFFFFu, local) & ~m;
        if (wbits && lane == 0)
            atomicOr(&g_done, wbits);               // RED: fire-and-forget
    }

    // ---- completion: last block writes output, resets persistent state.
    __threadfence();              // order this block's REDs before the ticket
    __syncthreads();
    if (tid == 0) s_ticket = atomicAdd(&g_count, 1u);
    __syncthreads();

    if (s_ticket == (unsigned)(gridDim.x - 1)) {
        __threadfence();                           // acquire side
        unsigned m = atomicOr(&g_done, 0u);        // coherent final mask
        for (int b = tid; b < out_size; b += PT)
            out[b] = (b < Bn) ? (float)((m >> b) & 1u) : 0.0f;
        __syncthreads();
        if (tid == 0) { g_done = 0u; g_count = 0u; }
    }
}

// ---------------------------------------------------------------------------
// Inputs (metadata order): pos[B,A,3] f32, eng[B] f32, elm[B,A] i32,
// radius[E] f32, eng_atm[E] f32, n[P] i32, i[P] i32, j[P] i32.
// Output: float32[B] (0.0 / 1.0).
extern "C" void kernel_launch(void* const* d_in, const int* in_sizes, int n_in,
                              void* d_out, int out_size) {
    const float* pos     = (const float*)d_in[0];
    const float* eng     = (const float*)d_in[1];
    const int*   elm     = (const int*)d_in[2];
    const float* radius  = (const float*)d_in[3];
    const float* eng_atm = (const float*)d_in[4];
    const int*   nn      = (const int*)d_in[5];
    const int*   ii      = (const int*)d_in[6];
    const int*   jj      = (const int*)d_in[7];
    int P = in_sizes[5];

    k_fused<<<NB, PT>>>(pos, eng, elm, radius, eng_atm, nn, ii, jj, P,
                        (float*)d_out, out_size);
}

// round 5
// speedup vs baseline: 1.3359x; 1.2630x over previous
#include <cuda_runtime.h>
#include <cuda_bf16.h>

// Problem constants (reference: B=32, A=4096, P=8388608, E=8)
#define Bn 32
#define An 4096
#define En 8

#define NBLK 64
#define PT 256
#define WPB (PT / 32)            // 8 warps/block
#define NW (NBLK * WPB)          // 512 warps
#define WTILE 128                // pairs per warp-tile (32 lanes x int4)

// Persistent device state. Zero at module load; last block resets after each
// run so every graph replay starts clean.
__device__ unsigned g_done;   // bit b => out[b]=1 (too_close OR eng_big)
__device__ unsigned g_count;  // completion ticket

__global__ void __launch_bounds__(PT)
k_fused(const float* __restrict__ pos,
        const float* __restrict__ eng,
        const int* __restrict__ elm,
        const float* __restrict__ radius,
        const float* __restrict__ eng_atm,
        const int* __restrict__ nn,
        const int* __restrict__ ii,
        const int* __restrict__ jj,
        int P,
        float* __restrict__ out, int out_size) {
    __shared__ float s_rad[En];
    __shared__ unsigned s_ticket;

    const int tid  = threadIdx.x;
    const int bid  = blockIdx.x;
    const int wid  = tid >> 5;
    const int lane = tid & 31;
    const int gw   = bid * WPB + wid;      // global warp id

    if (tid < En) s_rad[tid] = radius[tid];
    __syncthreads();

    // ---- Phase 1: pair scan. Grid-strided warp tiles so the globally FIRST
    // 65K pairs are scanned in iteration 0 (statistically resolves all 32
    // structures); loop covers all P pairs for correctness on any data.
    const long long ntiles = ((long long)P + WTILE - 1) / WTILE;
    unsigned m = 0u;

    for (long long t = gw; t < ntiles; t += NW) {
        m = __ldcg(&g_done);
        m = __shfl_sync(0xFFFFFFFFu, m, 0);        // warp-uniform
        if (m == 0xFFFFFFFFu) break;               // everything resolved

        long long idx = t * WTILE + lane * 4;
        unsigned local = 0u;

        if (idx + 4 <= (long long)P) {
            int4 n4 = __ldg((const int4*)(nn + idx));
            int4 i4 = __ldg((const int4*)(ii + idx));
            int4 j4 = __ldg((const int4*)(jj + idx));
            int na[4] = {n4.x, n4.y, n4.z, n4.w};
            int ia[4] = {i4.x, i4.y, i4.z, i4.w};
            int ja[4] = {j4.x, j4.y, j4.z, j4.w};
            #pragma unroll
            for (int k = 0; k < 4; ++k) {
                int nb = na[k];
                if ((m >> nb) & 1u) continue;
                int ai = nb * An + ia[k];
                int aj = nb * An + ja[k];
                float ax = __ldg(pos + 3 * ai + 0);
                float ay = __ldg(pos + 3 * ai + 1);
                float az = __ldg(pos + 3 * ai + 2);
                float bx = __ldg(pos + 3 * aj + 0);
                float by = __ldg(pos + 3 * aj + 1);
                float bz = __ldg(pos + 3 * aj + 2);
                float rs = s_rad[__ldg(elm + ai)] + s_rad[__ldg(elm + aj)];
                float dx = bx - ax, dy = by - ay, dz = bz - az;
                float sod = dx * dx + dy * dy + dz * dz;
                if (rs * rs >= sod) local |= 1u << nb;
            }
        } else if (idx < (long long)P) {
            for (int k = 0; k < 4; ++k) {
                long long q = idx + k;
                if (q >= (long long)P) break;
                int nb = __ldg(nn + q);
                if ((m >> nb) & 1u) continue;
                int ai = nb * An + __ldg(ii + q);
                int aj = nb * An + __ldg(jj + q);
                float dx = __ldg(pos + 3 * aj + 0) - __ldg(pos + 3 * ai + 0);
                float dy = __ldg(pos + 3 * aj + 1) - __ldg(pos + 3 * ai + 1);
                float dz = __ldg(pos + 3 * aj + 2) - __ldg(pos + 3 * ai + 2);
                float sod = dx * dx + dy * dy + dz * dz;
                float rs = s_rad[__ldg(elm + ai)] + s_rad[__ldg(elm + aj)];
                if (rs * rs >= sod) local |= 1u << nb;
            }
        }

        unsigned wbits = __reduce_or_sync(0xFFFFFFFFu, local) & ~m;
        if (wbits && lane == 0)
            atomicOr(&g_done, wbits);              // RED, fire-and-forget
        m |= wbits;
        if (m == 0xFFFFFFFFu) break;
    }

    // ---- Phase 2 (fallback, normally skipped): eng_big for structures the
    // pair scan did not flag. Warp 0 of block b (<32) handles structure b.
    if (bid < Bn && wid == 0) {
        unsigned cur = __ldcg(&g_done);
        cur = __shfl_sync(0xFFFFFFFFu, cur, 0);
        if (!((cur >> bid) & 1u)) {
            float av = __ldg(eng_atm + (lane & (En - 1)));
            const int4* row = (const int4*)(elm + bid * An);
            float s = 0.f;
            #pragma unroll 4
            for (int t2 = lane; t2 < An / 4; t2 += 32) {
                int4 e4 = __ldg(row + t2);
                s += __shfl_sync(0xFFFFFFFFu, av, e4.x & 7);
                s += __shfl_sync(0xFFFFFFFFu, av, e4.y & 7);
                s += __shfl_sync(0xFFFFFFFFu, av, e4.z & 7);
                s += __shfl_sync(0xFFFFFFFFu, av, e4.w & 7);
            }
            #pragma unroll
            for (int o = 16; o > 0; o >>= 1)
                s += __shfl_down_sync(0xFFFFFFFFu, s, o);
            s = __shfl_sync(0xFFFFFFFFu, s, 0);
            if (lane == 0 && __ldg(eng + bid) >= s)
                atomicOr(&g_done, 1u << bid);
        }
    }

    // ---- Completion: last block writes output, resets persistent state.
    __threadfence();
    __syncthreads();
    if (tid == 0) s_ticket = atomicAdd(&g_count, 1u);
    __syncthreads();

    if (s_ticket == (unsigned)(gridDim.x - 1)) {
        __threadfence();
        unsigned fm = atomicOr(&g_done, 0u);       // coherent final mask
        for (int b = tid; b < out_size; b += PT)
            out[b] = (b < Bn) ? (float)((fm >> b) & 1u) : 0.0f;
        __syncthreads();
        if (tid == 0) { g_done = 0u; g_count = 0u; }
    }
}

// ---------------------------------------------------------------------------
// Inputs (metadata order): pos[B,A,3] f32, eng[B] f32, elm[B,A] i32,
// radius[E] f32, eng_atm[E] f32, n[P] i32, i[P] i32, j[P] i32.
// Output: float32[B] (0.0 / 1.0).
extern "C" void kernel_launch(void* const* d_in, const int* in_sizes, int n_in,
                              void* d_out, int out_size) {
    const float* pos     = (const float*)d_in[0];
    const float* eng     = (const float*)d_in[1];
    const int*   elm     = (const int*)d_in[2];
    const float* radius  = (const float*)d_in[3];
    const float* eng_atm = (const float*)d_in[4];
    const int*   nn      = (const int*)d_in[5];
    const int*   ii      = (const int*)d_in[6];
    const int*   jj      = (const int*)d_in[7];
    int P = in_sizes[5];

    k_fused<<<NBLK, PT>>>(pos, eng, elm, radius, eng_atm, nn, ii, jj, P,
                          (float*)d_out, out_size);
}

// round 6
// speedup vs baseline: 1.8127x; 1.3569x over previous
#include <cuda_runtime.h>
#include <cuda_bf16.h>

// Problem constants (reference: B=32, A=4096, P=8388608, E=8)
#define Bn 32
#define An 4096
#define En 8

#define NBLK 64
#define PT 256
#define WPB (PT / 32)             // 8 warps/block
#define NW (NBLK * WPB)           // 512 warps
#define PREFIX (NW * 32)          // 16384 pairs scanned in stage A (1/lane)
#define WTILE 128                 // fallback tile (32 lanes x int4)
#define MAXSPIN 64

// Persistent device state. Zero at module load; last block resets after each
// run so every graph replay starts clean.
__device__ unsigned g_done;   // bit b => out[b]=1 (too_close OR eng_big)
__device__ unsigned g_count;  // completion ticket

__global__ void __launch_bounds__(PT)
k_fused(const float* __restrict__ pos,
        const float* __restrict__ eng,
        const int* __restrict__ elm,
        const float* __restrict__ radius,
        const float* __restrict__ eng_atm,
        const int* __restrict__ nn,
        const int* __restrict__ ii,
        const int* __restrict__ jj,
        int P,
        float* __restrict__ out, int out_size) {
    __shared__ float s_rad[En];
    __shared__ unsigned s_ticket;

    const int tid  = threadIdx.x;
    const int bid  = blockIdx.x;
    const int wid  = tid >> 5;
    const int lane = tid & 31;
    const int gw   = bid * WPB + wid;      // global warp id

    if (tid < En) s_rad[tid] = radius[tid];
    __syncthreads();

    // ---- Stage A: one pair per lane from the global prefix. No mask read,
    // no loop — single latency chain, then publish.
    {
        int q = gw * 32 + lane;
        unsigned local = 0u;
        if (q < P) {
            int nb = __ldg(nn + q);
            int ai = nb * An + __ldg(ii + q);
            int aj = nb * An + __ldg(jj + q);
            float ax = __ldg(pos + 3 * ai + 0);
            float ay = __ldg(pos + 3 * ai + 1);
            float az = __ldg(pos + 3 * ai + 2);
            float bx = __ldg(pos + 3 * aj + 0);
            float by = __ldg(pos + 3 * aj + 1);
            float bz = __ldg(pos + 3 * aj + 2);
            float rs = s_rad[__ldg(elm + ai)] + s_rad[__ldg(elm + aj)];
            float dx = bx - ax, dy = by - ay, dz = bz - az;
            float sod = dx * dx + dy * dy + dz * dz;
            if (rs * rs >= sod) local = 1u << nb;
        }
        unsigned wbits = __reduce_or_sync(0xFFFFFFFFu, local);
        if (wbits && lane == 0)
            atomicOr(&g_done, wbits);          // RED, fire-and-forget
    }

    // ---- Bounded spin on the 4-byte mask (cheap polls, not tile re-evals).
    unsigned m = 0u;
    for (int s = 0; s < MAXSPIN; ++s) {
        m = __ldcg(&g_done);                   // same addr all lanes: broadcast
        if (m == 0xFFFFFFFFu) break;
        __nanosleep(40);
    }

    if (m != 0xFFFFFFFFu) {
        // ---- Fallback 1: grid-strided scan of the remaining pairs,
        // polling between tiles. Covers [PREFIX, P).
        const long long ntiles =
            ((long long)P - PREFIX + WTILE - 1) / WTILE;
        for (long long t = gw; t < ntiles; t += NW) {
            m = __ldcg(&g_done);
            if (m == 0xFFFFFFFFu) break;

            long long idx = (long long)PREFIX + t * WTILE + lane * 4;
            unsigned local = 0u;
            if (idx + 4 <= (long long)P) {
                int4 n4 = __ldg((const int4*)(nn + idx));
                int4 i4 = __ldg((const int4*)(ii + idx));
                int4 j4 = __ldg((const int4*)(jj + idx));
                int na[4] = {n4.x, n4.y, n4.z, n4.w};
                int ia[4] = {i4.x, i4.y, i4.z, i4.w};
                int ja[4] = {j4.x, j4.y, j4.z, j4.w};
                #pragma unroll
                for (int k = 0; k < 4; ++k) {
                    int nb = na[k];
                    if ((m >> nb) & 1u) continue;
                    int ai = nb * An + ia[k];
                    int aj = nb * An + ja[k];
                    float dx = __ldg(pos + 3 * aj + 0) - __ldg(pos + 3 * ai + 0);
                    float dy = __ldg(pos + 3 * aj + 1) - __ldg(pos + 3 * ai + 1);
                    float dz = __ldg(pos + 3 * aj + 2) - __ldg(pos + 3 * ai + 2);
                    float sod = dx * dx + dy * dy + dz * dz;
                    float rs = s_rad[__ldg(elm + ai)] + s_rad[__ldg(elm + aj)];
                    if (rs * rs >= sod) local |= 1u << nb;
                }
            } else if (idx < (long long)P) {
                for (int k = 0; k < 4; ++k) {
                    long long q = idx + k;
                    if (q >= (long long)P) break;
                    int nb = __ldg(nn + q);
                    if ((m >> nb) & 1u) continue;
                    int ai = nb * An + __ldg(ii + q);
                    int aj = nb * An + __ldg(jj + q);
                    float dx = __ldg(pos + 3 * aj + 0) - __ldg(pos + 3 * ai + 0);
                    float dy = __ldg(pos + 3 * aj + 1) - __ldg(pos + 3 * ai + 1);
                    float dz = __ldg(pos + 3 * aj + 2) - __ldg(pos + 3 * ai + 2);
                    float sod = dx * dx + dy * dy + dz * dz;
                    float rs = s_rad[__ldg(elm + ai)] + s_rad[__ldg(elm + aj)];
                    if (rs * rs >= sod) local |= 1u << nb;
                }
            }
            unsigned wbits = __reduce_or_sync(0xFFFFFFFFu, local) & ~m;
            if (wbits && lane == 0)
                atomicOr(&g_done, wbits);
            m |= wbits;
            if (m == 0xFFFFFFFFu) break;
        }

        // ---- Fallback 2: eng_big reduction for structures still unflagged.
        // Warp 0 of block b (<32) handles structure b.
        if (bid < Bn && wid == 0) {
            unsigned cur = __ldcg(&g_done);
            if (!((cur >> bid) & 1u)) {
                float av = __ldg(eng_atm + (lane & (En - 1)));
                const int4* row = (const int4*)(elm + bid * An);
                float s = 0.f;
                #pragma unroll 4
                for (int t2 = lane; t2 < An / 4; t2 += 32) {
                    int4 e4 = __ldg(row + t2);
                    s += __shfl_sync(0xFFFFFFFFu, av, e4.x & 7);
                    s += __shfl_sync(0xFFFFFFFFu, av, e4.y & 7);
                    s += __shfl_sync(0xFFFFFFFFu, av, e4.z & 7);
                    s += __shfl_sync(0xFFFFFFFFu, av, e4.w & 7);
                }
                #pragma unroll
                for (int o = 16; o > 0; o >>= 1)
                    s += __shfl_down_sync(0xFFFFFFFFu, s, o);
                s = __shfl_sync(0xFFFFFFFFu, s, 0);
                if (lane == 0 && __ldg(eng + bid) >= s)
                    atomicOr(&g_done, 1u << bid);
            }
        }
    }

    // ---- Completion: last block writes output, resets persistent state.
    __threadfence();
    __syncthreads();
    if (tid == 0) s_ticket = atomicAdd(&g_count, 1u);
    __syncthreads();

    if (s_ticket == (unsigned)(gridDim.x - 1)) {
        __threadfence();
        unsigned fm = atomicOr(&g_done, 0u);   // coherent final mask
        for (int b = tid; b < out_size; b += PT)
            out[b] = (b < Bn) ? (float)((fm >> b) & 1u) : 0.0f;
        __syncthreads();
        if (tid == 0) { g_done = 0u; g_count = 0u; }
    }
}

// ---------------------------------------------------------------------------
// Inputs (metadata order): pos[B,A,3] f32, eng[B] f32, elm[B,A] i32,
// radius[E] f32, eng_atm[E] f32, n[P] i32, i[P] i32, j[P] i32.
// Output: float32[B] (0.0 / 1.0).
extern "C" void kernel_launch(void* const* d_in, const int* in_sizes, int n_in,
                              void* d_out, int out_size) {
    const float* pos     = (const float*)d_in[0];
    const float* eng     = (const float*)d_in[1];
    const int*   elm     = (const int*)d_in[2];
    const float* radius  = (const float*)d_in[3];
    const float* eng_atm = (const float*)d_in[4];
    const int*   nn      = (const int*)d_in[5];
    const int*   ii      = (const int*)d_in[6];
    const int*   jj      = (const int*)d_in[7];
    int P = in_sizes[5];

    k_fused<<<NBLK, PT>>>(pos, eng, elm, radius, eng_atm, nn, ii, jj, P,
                          (float*)d_out, out_size);
}